// round 7
// baseline (speedup 1.0000x reference)
#include <cuda_runtime.h>
#include <cuda_fp16.h>
#include <cstdint>

// ======================= problem constants =======================
#define SEQ      8192
#define HD       128
#define MT       64                  // M tile (rows of S per CTA)
#define KT       64                  // K tile (cols of S per iteration)
#define KSPLITS  16
#define KCOLS    (SEQ / KSPLITS)     // 512 cols per split
#define NTILES   (KCOLS / KT)        // 8 iterations per CTA
#define THREADS  256

#define PSTRIDE_H   72               // halves per smem row (64 data + 8 pad)
#define PSTRIDE_B   (PSTRIDE_H * 2)  // 144 bytes
#define PTILE_BYTES (MT  * PSTRIDE_B)   // 9216 B  (P tile: 64 rows)
#define VTILE_BYTES (128 * PSTRIDE_B)   // 18432 B (V tile: 128 rows)
#define SM_TOTAL    (2 * PTILE_BYTES + 2 * VTILE_BYTES)  // 55296 B

// ======================= device scratch (no cudaMalloc allowed) ==
__device__ float  g_O[SEQ * HD];     // 4 MB accumulated numerators (atomic)
__device__ float  g_l[SEQ];          // accumulated denominators (atomic)
__device__ __half g_Vh[HD * SEQ];    // V_T pre-converted to fp16

// ======================= PTX helpers =============================
__device__ __forceinline__ uint32_t smem_u32(const void* p) {
    uint32_t a;
    asm("{ .reg .u64 t; cvta.to.shared.u64 t, %1; cvt.u32.u64 %0, t; }" : "=r"(a) : "l"(p));
    return a;
}

__device__ __forceinline__ void ldmatrix_x4(uint32_t* r, uint32_t addr) {
    asm volatile("ldmatrix.sync.aligned.m8n8.x4.shared.b16 {%0,%1,%2,%3}, [%4];"
                 : "=r"(r[0]), "=r"(r[1]), "=r"(r[2]), "=r"(r[3]) : "r"(addr));
}

__device__ __forceinline__ void mma16816(float* c, const uint32_t* a, const uint32_t* b) {
    asm volatile("mma.sync.aligned.m16n8k16.row.col.f32.f16.f16.f32 "
                 "{%0,%1,%2,%3}, {%4,%5,%6,%7}, {%8,%9}, {%0,%1,%2,%3};"
                 : "+f"(c[0]), "+f"(c[1]), "+f"(c[2]), "+f"(c[3])
                 : "r"(a[0]), "r"(a[1]), "r"(a[2]), "r"(a[3]), "r"(b[0]), "r"(b[1]));
}

#define CP_ASYNC16(dst, src) \
    asm volatile("cp.async.cg.shared.global [%0], [%1], 16;" :: "r"(dst), "l"(src))
#define CP_COMMIT() asm volatile("cp.async.commit_group;" ::: "memory")
#define CP_WAIT(n)  asm volatile("cp.async.wait_group %0;" :: "n"(n) : "memory")

// ======================= kernel 1: prep (convert V + zero acc) ===
// blocks [0, 1024): convert V_T fp32 -> fp16 (one float4 per thread)
// blocks [1024, 2048): zero g_O (one float4 per thread) + g_l
__global__ void prep_kernel(const float* __restrict__ VT) {
    const int b = blockIdx.x;
    if (b < 1024) {
        const int i = (b * 256 + threadIdx.x) * 4;
        float4 v = *reinterpret_cast<const float4*>(VT + i);
        union { __half2 h[2]; uint2 u; } c;
        c.h[0] = __floats2half2_rn(v.x, v.y);
        c.h[1] = __floats2half2_rn(v.z, v.w);
        *reinterpret_cast<uint2*>(&g_Vh[i]) = c.u;
    } else {
        const int t = (b - 1024) * 256 + threadIdx.x;
        *reinterpret_cast<float4*>(&g_O[t * 4]) = make_float4(0.f, 0.f, 0.f, 0.f);
        if (t < SEQ / 4)
            *reinterpret_cast<float4*>(&g_l[t * 4]) = make_float4(0.f, 0.f, 0.f, 0.f);
    }
}

// ======================= kernel 2: main streaming flash ==========
__global__ void __launch_bounds__(THREADS, 2)
flash_main_kernel(const float* __restrict__ S) {
    extern __shared__ char smem[];
    const int tid = threadIdx.x;
    const int lid = tid & 31;
    const int wid = tid >> 5;
    const int m0 = blockIdx.x * MT;
    const int ks = blockIdx.y;
    const int k0 = ks * KCOLS;

    char* pbuf[2] = { smem,                   smem + PTILE_BYTES };
    char* vbuf[2] = { smem + 2 * PTILE_BYTES, smem + 2 * PTILE_BYTES + VTILE_BYTES };

    // ---- S load mapping: 64 rows x 16 float4 per row; each thread 4 rows
    const int su  = tid & 15;        // float4 slot within row
    const int sr0 = tid >> 4;        // base row (0..15); rows sr0 + 16*j
    // ---- V load mapping: 128 rows x 8 uint4 per row; each thread 4 rows
    const int vu  = tid & 7;
    const int vr0 = tid >> 3;        // 0..31; rows vr0 + 32*j

    const float* Srow[4];
#pragma unroll
    for (int j = 0; j < 4; j++)
        Srow[j] = S + (size_t)(m0 + sr0 + 16 * j) * SEQ + k0 + su * 4;

    float rs[4] = {0.f, 0.f, 0.f, 0.f};

    // ---- prologue: load S(0), cp.async V(0), convert(0) -> pbuf[0], load S(1)
    float4 stage[4];
#pragma unroll
    for (int j = 0; j < 4; j++)
        stage[j] = __ldcs(reinterpret_cast<const float4*>(Srow[j]));
    {
        const __half* vsrc = g_Vh + (size_t)vr0 * SEQ + k0 + vu * 8;
#pragma unroll
        for (int j = 0; j < 4; j++)
            CP_ASYNC16(smem_u32(vbuf[0] + (vr0 + 32 * j) * PSTRIDE_B + vu * 16),
                       vsrc + (size_t)(32 * j) * SEQ);
        CP_COMMIT();
    }
#pragma unroll
    for (int j = 0; j < 4; j++) {
        float e0 = __expf(stage[j].x), e1 = __expf(stage[j].y);
        float e2 = __expf(stage[j].z), e3 = __expf(stage[j].w);
        rs[j] += (e0 + e1) + (e2 + e3);
        union { __half2 h[2]; uint2 u; } c;
        c.h[0] = __floats2half2_rn(e0, e1);
        c.h[1] = __floats2half2_rn(e2, e3);
        *reinterpret_cast<uint2*>(pbuf[0] + (sr0 + 16 * j) * PSTRIDE_B + su * 8) = c.u;
    }
#pragma unroll
    for (int j = 0; j < 4; j++)
        stage[j] = __ldcs(reinterpret_cast<const float4*>(Srow[j] + KT));

    float acc[2][4][4];
#pragma unroll
    for (int a = 0; a < 2; a++)
#pragma unroll
        for (int b = 0; b < 4; b++)
#pragma unroll
            for (int c = 0; c < 4; c++) acc[a][b][c] = 0.0f;

    const int wm = wid >> 2;         // 0..1: 32-row band
    const int wn = wid & 3;          // 0..3: 32-col band

#pragma unroll 1
    for (int t = 0; t < NTILES; t++) {
        const int cur = t & 1;

        // ---- drain own V(t) copies, then make everything visible to all warps.
        // Barrier orders: V(t) cp.async writes -> MMA(t) reads;
        //                convert(t) P writes   -> MMA(t) reads;
        //                MMA(t-1) V reads      -> V(t+1) cp.async writes.
        CP_WAIT(0);
        __syncthreads();

        // ---- issue V(t+1) prefetch into the buffer MMA(t-1) just released
        if (t < NTILES - 1) {
            const __half* vsrc = g_Vh + (size_t)vr0 * SEQ + k0 + (t + 1) * KT + vu * 8;
#pragma unroll
            for (int j = 0; j < 4; j++)
                CP_ASYNC16(smem_u32(vbuf[cur ^ 1] + (vr0 + 32 * j) * PSTRIDE_B + vu * 16),
                           vsrc + (size_t)(32 * j) * SEQ);
            CP_COMMIT();
        }

        // ---- MMA(t): warp (wm, wn) computes 32x32 over K=64 from pbuf[cur]
        {
            const uint32_t pB = smem_u32(pbuf[cur]);
            const uint32_t vB = smem_u32(vbuf[cur]);
#pragma unroll
            for (int kk = 0; kk < 4; kk++) {
                uint32_t a[2][4];
#pragma unroll
                for (int mt = 0; mt < 2; mt++) {
                    uint32_t addr = pB + (wm * 32 + mt * 16 + (lid & 15)) * PSTRIDE_B
                                       + (kk * 16 + (lid >> 4) * 8) * 2;
                    ldmatrix_x4(a[mt], addr);
                }
#pragma unroll
                for (int np = 0; np < 2; np++) {
                    uint32_t b[4];
                    const int n    = wn * 32 + np * 16 + (lid >> 4) * 8 + (lid & 7);
                    const int koff = kk * 16 + ((lid >> 3) & 1) * 8;
                    ldmatrix_x4(b, vB + n * PSTRIDE_B + koff * 2);
#pragma unroll
                    for (int mt = 0; mt < 2; mt++) {
                        mma16816(acc[mt][np * 2 + 0], a[mt], b + 0);
                        mma16816(acc[mt][np * 2 + 1], a[mt], b + 2);
                    }
                }
            }
        }

        // ---- convert(t+1) into the other P buffer (co-issues with MMA across warps)
        if (t < NTILES - 1) {
#pragma unroll
            for (int j = 0; j < 4; j++) {
                float e0 = __expf(stage[j].x), e1 = __expf(stage[j].y);
                float e2 = __expf(stage[j].z), e3 = __expf(stage[j].w);
                rs[j] += (e0 + e1) + (e2 + e3);
                union { __half2 h[2]; uint2 u; } c;
                c.h[0] = __floats2half2_rn(e0, e1);
                c.h[1] = __floats2half2_rn(e2, e3);
                *reinterpret_cast<uint2*>(pbuf[cur ^ 1] + (sr0 + 16 * j) * PSTRIDE_B + su * 8) = c.u;
            }
            if (t < NTILES - 2) {
#pragma unroll
                for (int j = 0; j < 4; j++)
                    stage[j] = __ldcs(reinterpret_cast<const float4*>(Srow[j] + (t + 2) * KT));
            }
        }
    }

    // ---- row-sum partials: reduce over the 16-lane row group, atomic add
#pragma unroll
    for (int j = 0; j < 4; j++) {
        float v = rs[j];
        v += __shfl_xor_sync(0xffffffffu, v, 8);
        v += __shfl_xor_sync(0xffffffffu, v, 4);
        v += __shfl_xor_sync(0xffffffffu, v, 2);
        v += __shfl_xor_sync(0xffffffffu, v, 1);
        if ((lid & 15) == 0)
            atomicAdd(&g_l[m0 + sr0 + 16 * j], v);
    }

    // ---- accumulate partial numerators into global accumulator
#pragma unroll
    for (int mt = 0; mt < 2; mt++) {
#pragma unroll
        for (int nt = 0; nt < 4; nt++) {
            const int row = m0 + wm * 32 + mt * 16 + (lid >> 2);
            const int col = wn * 32 + nt * 8 + (lid & 3) * 2;
            atomicAdd(&g_O[(size_t)row * HD + col],           acc[mt][nt][0]);
            atomicAdd(&g_O[(size_t)row * HD + col + 1],       acc[mt][nt][1]);
            atomicAdd(&g_O[(size_t)(row + 8) * HD + col],     acc[mt][nt][2]);
            atomicAdd(&g_O[(size_t)(row + 8) * HD + col + 1], acc[mt][nt][3]);
        }
    }
}

// ======================= kernel 3: combine (float4) ==============
__global__ void combine_kernel(float* __restrict__ out) {
    const int idx = blockIdx.x * blockDim.x + threadIdx.x;   // over (8192*128)/4
    const int q = idx >> 5;                                  // 32 float4 per row
    float4 acc = *reinterpret_cast<const float4*>(&g_O[idx * 4]);
    float inv = 1.0f / g_l[q];
    acc.x *= inv; acc.y *= inv; acc.z *= inv; acc.w *= inv;
    *reinterpret_cast<float4*>(out + idx * 4) = acc;
}

// ======================= launch ==================================
extern "C" void kernel_launch(void* const* d_in, const int* in_sizes, int n_in,
                              void* d_out, int out_size) {
    const float* S  = (const float*)d_in[0];   // [8192, 8192]
    const float* VT = (const float*)d_in[1];   // [128, 8192]
    float* out = (float*)d_out;                // [8192, 128]

    cudaFuncSetAttribute(flash_main_kernel,
                         cudaFuncAttributeMaxDynamicSharedMemorySize, SM_TOTAL);

    prep_kernel<<<2048, 256>>>(VT);
    dim3 grid(SEQ / MT, KSPLITS);
    flash_main_kernel<<<grid, THREADS, SM_TOTAL>>>(S);
    combine_kernel<<<(SEQ * HD / 4) / 256, 256>>>(out);
}

// round 10
// speedup vs baseline: 1.2344x; 1.2344x over previous
#include <cuda_runtime.h>
#include <cuda_fp16.h>
#include <cstdint>

// ======================= problem constants =======================
#define SEQ      8192
#define HD       128
#define MT       64                  // M tile (rows of S per CTA)
#define KT       64                  // K tile (cols of S per iteration)
#define KSPLITS  8
#define KCOLS    (SEQ / KSPLITS)     // 1024 cols per split
#define NTILES   (KCOLS / KT)        // 16 iterations per CTA
#define THREADS  256

#define PSTRIDE_H   72               // halves per smem row (64 data + 8 pad)
#define PSTRIDE_B   (PSTRIDE_H * 2)  // 144 bytes
#define PTILE_BYTES (MT  * PSTRIDE_B)   // 9216 B  (P tile: 64 rows)
#define VTILE_BYTES (128 * PSTRIDE_B)   // 18432 B (V tile: 128 rows)
#define SM_TOTAL    (2 * PTILE_BYTES + 2 * VTILE_BYTES)  // 55296 B

// ======================= device scratch (no cudaMalloc allowed) ==
__device__ float  g_Opart[KSPLITS][SEQ * HD];   // 32 MB partial numerators
__device__ float  g_lpart[KSPLITS][SEQ];        // partial denominators
__device__ __half g_Vh[HD * SEQ];               // V_T pre-converted to fp16

// ======================= PTX helpers =============================
__device__ __forceinline__ uint32_t smem_u32(const void* p) {
    uint32_t a;
    asm("{ .reg .u64 t; cvta.to.shared.u64 t, %1; cvt.u32.u64 %0, t; }" : "=r"(a) : "l"(p));
    return a;
}

__device__ __forceinline__ void ldmatrix_x4(uint32_t* r, uint32_t addr) {
    asm volatile("ldmatrix.sync.aligned.m8n8.x4.shared.b16 {%0,%1,%2,%3}, [%4];"
                 : "=r"(r[0]), "=r"(r[1]), "=r"(r[2]), "=r"(r[3]) : "r"(addr));
}

__device__ __forceinline__ void mma16816(float* c, const uint32_t* a, const uint32_t* b) {
    asm volatile("mma.sync.aligned.m16n8k16.row.col.f32.f16.f16.f32 "
                 "{%0,%1,%2,%3}, {%4,%5,%6,%7}, {%8,%9}, {%0,%1,%2,%3};"
                 : "+f"(c[0]), "+f"(c[1]), "+f"(c[2]), "+f"(c[3])
                 : "r"(a[0]), "r"(a[1]), "r"(a[2]), "r"(a[3]), "r"(b[0]), "r"(b[1]));
}

#define CP_ASYNC16(dst, src) \
    asm volatile("cp.async.cg.shared.global [%0], [%1], 16;" :: "r"(dst), "l"(src))
#define CP_COMMIT() asm volatile("cp.async.commit_group;" ::: "memory")
#define CP_WAIT(n)  asm volatile("cp.async.wait_group %0;" :: "n"(n) : "memory")

// ======================= kernel 1: V_T fp32 -> fp16 (MLP=4) ======
__global__ void convert_v_kernel(const float* __restrict__ VT) {
    const int base = (blockIdx.x * blockDim.x + threadIdx.x) * 4;
    const int stride = gridDim.x * blockDim.x * 4;
    float4 v[4];
#pragma unroll
    for (int j = 0; j < 4; j++)
        v[j] = *reinterpret_cast<const float4*>(VT + base + j * stride);
#pragma unroll
    for (int j = 0; j < 4; j++) {
        union { __half2 h[2]; uint2 u; } c;
        c.h[0] = __floats2half2_rn(v[j].x, v[j].y);
        c.h[1] = __floats2half2_rn(v[j].z, v[j].w);
        *reinterpret_cast<uint2*>(&g_Vh[base + j * stride]) = c.u;
    }
}

// ======================= kernel 2: main streaming flash ==========
__global__ void __launch_bounds__(THREADS, 2)
flash_main_kernel(const float* __restrict__ S) {
    extern __shared__ char smem[];
    const int tid = threadIdx.x;
    const int lid = tid & 31;
    const int wid = tid >> 5;
    const int m0 = blockIdx.x * MT;
    const int ks = blockIdx.y;
    const int k0 = ks * KCOLS;

    char* pbuf[2] = { smem,                   smem + PTILE_BYTES };
    char* vbuf[2] = { smem + 2 * PTILE_BYTES, smem + 2 * PTILE_BYTES + VTILE_BYTES };

    // ---- S load mapping: 64 rows x 16 float4 per row; each thread 4 rows
    const int su  = tid & 15;        // float4 slot within row
    const int sr0 = tid >> 4;        // base row (0..15); rows sr0 + 16*j
    // ---- V load mapping: 128 rows x 8 uint4 per row; each thread 4 rows
    const int vu  = tid & 7;
    const int vr0 = tid >> 3;        // 0..31; rows vr0 + 32*j

    const float* Srow[4];
#pragma unroll
    for (int j = 0; j < 4; j++)
        Srow[j] = S + (size_t)(m0 + sr0 + 16 * j) * SEQ + k0 + su * 4;

    float rs[4] = {0.f, 0.f, 0.f, 0.f};

    // ---- prologue: depth-2 S prefetch + V(0) cp.async
    // stage[p] holds S(t) for t with t&1 == p.
    float4 stage[2][4];
#pragma unroll
    for (int j = 0; j < 4; j++)
        stage[0][j] = __ldcs(reinterpret_cast<const float4*>(Srow[j]));
    {
        const __half* vsrc = g_Vh + (size_t)vr0 * SEQ + k0 + vu * 8;
#pragma unroll
        for (int j = 0; j < 4; j++)
            CP_ASYNC16(smem_u32(vbuf[0] + (vr0 + 32 * j) * PSTRIDE_B + vu * 16),
                       vsrc + (size_t)(32 * j) * SEQ);
        CP_COMMIT();
    }
#pragma unroll
    for (int j = 0; j < 4; j++)
        stage[1][j] = __ldcs(reinterpret_cast<const float4*>(Srow[j] + KT));

    float acc[2][4][4];
#pragma unroll
    for (int a = 0; a < 2; a++)
#pragma unroll
        for (int b = 0; b < 4; b++)
#pragma unroll
            for (int c = 0; c < 4; c++) acc[a][b][c] = 0.0f;

    const int wm = wid >> 2;         // 0..1: 32-row band
    const int wn = wid & 3;          // 0..3: 32-col band

#pragma unroll 2
    for (int t = 0; t < NTILES; t++) {
        const int cur = t & 1;
        const int p   = t & 1;       // stage slot holding S(t)

        // ---- prefetch V(t+1) into other buffer; wait for V(t)
        if (t < NTILES - 1) {
            const __half* vsrc = g_Vh + (size_t)vr0 * SEQ + k0 + (t + 1) * KT + vu * 8;
#pragma unroll
            for (int j = 0; j < 4; j++)
                CP_ASYNC16(smem_u32(vbuf[cur ^ 1] + (vr0 + 32 * j) * PSTRIDE_B + vu * 16),
                           vsrc + (size_t)(32 * j) * SEQ);
            CP_COMMIT();
            CP_WAIT(1);
        } else {
            CP_WAIT(0);
        }

        // ---- convert S(t): exp -> fp16 -> pbuf[cur]; accumulate row sums
#pragma unroll
        for (int j = 0; j < 4; j++) {
            float e0 = __expf(stage[p][j].x), e1 = __expf(stage[p][j].y);
            float e2 = __expf(stage[p][j].z), e3 = __expf(stage[p][j].w);
            rs[j] += (e0 + e1) + (e2 + e3);
            union { __half2 h[2]; uint2 u; } c;
            c.h[0] = __floats2half2_rn(e0, e1);
            c.h[1] = __floats2half2_rn(e2, e3);
            *reinterpret_cast<uint2*>(pbuf[cur] + (sr0 + 16 * j) * PSTRIDE_B + su * 8) = c.u;
        }
        // ---- issue S(t+2) into the stage slot just consumed (2-iter cover)
        if (t < NTILES - 2) {
#pragma unroll
            for (int j = 0; j < 4; j++)
                stage[p][j] = __ldcs(reinterpret_cast<const float4*>(Srow[j] + (t + 2) * KT));
        }
        __syncthreads();

        // ---- MMA(t): warp (wm, wn) computes 32x32 over K=64
        const uint32_t pB = smem_u32(pbuf[cur]);
        const uint32_t vB = smem_u32(vbuf[cur]);
#pragma unroll
        for (int kk = 0; kk < 4; kk++) {
            uint32_t a[2][4];
#pragma unroll
            for (int mt = 0; mt < 2; mt++) {
                uint32_t addr = pB + (wm * 32 + mt * 16 + (lid & 15)) * PSTRIDE_B
                                   + (kk * 16 + (lid >> 4) * 8) * 2;
                ldmatrix_x4(a[mt], addr);
            }
#pragma unroll
            for (int np = 0; np < 2; np++) {
                uint32_t b[4];
                const int n    = wn * 32 + np * 16 + (lid >> 4) * 8 + (lid & 7);
                const int koff = kk * 16 + ((lid >> 3) & 1) * 8;
                ldmatrix_x4(b, vB + n * PSTRIDE_B + koff * 2);
#pragma unroll
                for (int mt = 0; mt < 2; mt++) {
                    mma16816(acc[mt][np * 2 + 0], a[mt], b + 0);
                    mma16816(acc[mt][np * 2 + 1], a[mt], b + 2);
                }
            }
        }
        __syncthreads();
    }

    // ---- row-sum partials: reduce over the 16-lane row group
#pragma unroll
    for (int j = 0; j < 4; j++) {
        float v = rs[j];
        v += __shfl_xor_sync(0xffffffffu, v, 8);
        v += __shfl_xor_sync(0xffffffffu, v, 4);
        v += __shfl_xor_sync(0xffffffffu, v, 2);
        v += __shfl_xor_sync(0xffffffffu, v, 1);
        if ((lid & 15) == 0)
            g_lpart[ks][m0 + sr0 + 16 * j] = v;
    }

    // ---- store partial numerators (streaming: keep L2 for S)
    float* op = g_Opart[ks];
#pragma unroll
    for (int mt = 0; mt < 2; mt++) {
#pragma unroll
        for (int nt = 0; nt < 4; nt++) {
            const int row = m0 + wm * 32 + mt * 16 + (lid >> 2);
            const int col = wn * 32 + nt * 8 + (lid & 3) * 2;
            __stcg(reinterpret_cast<float2*>(&op[(size_t)row * HD + col]),
                   make_float2(acc[mt][nt][0], acc[mt][nt][1]));
            __stcg(reinterpret_cast<float2*>(&op[(size_t)(row + 8) * HD + col]),
                   make_float2(acc[mt][nt][2], acc[mt][nt][3]));
        }
    }
}

// ======================= kernel 3: combine (float4) ==============
__global__ void combine_kernel(float* __restrict__ out) {
    const int idx = blockIdx.x * blockDim.x + threadIdx.x;   // over (8192*128)/4
    const int q = idx >> 5;                                  // 32 float4 per row
    float4 acc = make_float4(0.f, 0.f, 0.f, 0.f);
    float l = 0.0f;
#pragma unroll
    for (int s = 0; s < KSPLITS; s++) {
        float4 p = *reinterpret_cast<const float4*>(&g_Opart[s][idx * 4]);
        acc.x += p.x; acc.y += p.y; acc.z += p.z; acc.w += p.w;
        l += g_lpart[s][q];
    }
    float inv = 1.0f / l;
    acc.x *= inv; acc.y *= inv; acc.z *= inv; acc.w *= inv;
    *reinterpret_cast<float4*>(out + idx * 4) = acc;
}

// ======================= launch ==================================
extern "C" void kernel_launch(void* const* d_in, const int* in_sizes, int n_in,
                              void* d_out, int out_size) {
    const float* S  = (const float*)d_in[0];   // [8192, 8192]
    const float* VT = (const float*)d_in[1];   // [128, 8192]
    float* out = (float*)d_out;                // [8192, 128]

    cudaFuncSetAttribute(flash_main_kernel,
                         cudaFuncAttributeMaxDynamicSharedMemorySize, SM_TOTAL);

    convert_v_kernel<<<(HD * SEQ) / (256 * 16), 256>>>(VT);
    dim3 grid(SEQ / MT, KSPLITS);
    flash_main_kernel<<<grid, THREADS, SM_TOTAL>>>(S);
    combine_kernel<<<(SEQ * HD / 4) / 256, 256>>>(out);
}